// round 1
// baseline (speedup 1.0000x reference)
#include <cuda_runtime.h>
#include <math.h>

#define B_  16
#define N_  1024
#define C_  768
#define NH  12
#define HD_ 64
#define QC  2496   // 3*768 + 3*64
#define XC  832    // 768 + 64
#define M1_INV (1.0f/12582912.0f)  // b*H*n*d
#define M2_INV (1.0f/1048576.0f)   // b*64*32*32
#define LR_ 0.001f

// ---------------- scratch (static device memory; no allocations) ----------------
__device__ float g_qkv[B_*N_*QC];                 // 163.6 MB
__device__ float g_xcat[B_*N_*XC];                // 54.5 MB
__device__ float g_gw_part[2*NH*128*HD_*HD_];     // 50 MB  (deterministic partials)
__device__ float g_gw[2*NH*HD_*HD_];
__device__ float g_gw3_part[B_*64*9];
__device__ float g_gw3[64*9];
__device__ float g_sumsq[25];                     // 0..11 w1 heads, 12..23 w2 heads, 24 w3
__device__ float g_scales[3];
__device__ float g_mw1[NH*HD_*HD_];
__device__ float g_mw2[NH*HD_*HD_];
__device__ float g_mw3[64*9];

// ---------------- generic SGEMM: C = A[MxK] * B[KxN] + bias ----------------
// 128x128 tile, BK=8, 256 threads, 8x8 register tile. K % 8 == 0, M % 128 == 0,
// N arbitrary multiple of 4 (guarded).
__global__ __launch_bounds__(256) void sgemm_bias(
    const float* __restrict__ A, const float* __restrict__ Bm,
    const float* __restrict__ bias, float* __restrict__ C,
    int M, int N, int K)
{
    __shared__ float As[8][128];
    __shared__ float Bs[8][128];
    const int tid  = threadIdx.x;
    const int row0 = blockIdx.y * 128;
    const int col0 = blockIdx.x * 128;
    const int ty = tid >> 4, tx = tid & 15;
    const int trow = ty * 8, tcol = tx * 8;
    const int a_r = (tid * 4) >> 3, a_c = (tid * 4) & 7;
    const int b_r = (tid * 4) >> 7, b_c = (tid * 4) & 127;

    float acc[8][8];
#pragma unroll
    for (int i = 0; i < 8; i++)
#pragma unroll
        for (int j = 0; j < 8; j++) acc[i][j] = 0.f;

    for (int k0 = 0; k0 < K; k0 += 8) {
        float4 av = *(const float4*)(A + (size_t)(row0 + a_r) * K + k0 + a_c);
        float4 bv = make_float4(0.f, 0.f, 0.f, 0.f);
        if (col0 + b_c < N)
            bv = *(const float4*)(Bm + (size_t)(k0 + b_r) * N + col0 + b_c);
        __syncthreads();
        As[a_c + 0][a_r] = av.x;
        As[a_c + 1][a_r] = av.y;
        As[a_c + 2][a_r] = av.z;
        As[a_c + 3][a_r] = av.w;
        *(float4*)&Bs[b_r][b_c] = bv;
        __syncthreads();
#pragma unroll
        for (int kk = 0; kk < 8; kk++) {
            float a[8], b[8];
            *(float4*)&a[0] = *(float4*)&As[kk][trow];
            *(float4*)&a[4] = *(float4*)&As[kk][trow + 4];
            *(float4*)&b[0] = *(float4*)&Bs[kk][tcol];
            *(float4*)&b[4] = *(float4*)&Bs[kk][tcol + 4];
#pragma unroll
            for (int i = 0; i < 8; i++)
#pragma unroll
                for (int j = 0; j < 8; j++)
                    acc[i][j] = fmaf(a[i], b[j], acc[i][j]);
        }
    }

#pragma unroll
    for (int i = 0; i < 8; i++) {
        const int row = row0 + trow + i;
#pragma unroll
        for (int j = 0; j < 8; j += 4) {
            const int col = col0 + tcol + j;
            if (col < N) {
                float4 o;
                o.x = acc[i][j + 0] + bias[col + 0];
                o.y = acc[i][j + 1] + bias[col + 1];
                o.z = acc[i][j + 2] + bias[col + 2];
                o.w = acc[i][j + 3] + bias[col + 3];
                *(float4*)(C + (size_t)row * N + col) = o;
            }
        }
    }
}

// ---------------- TTT gradient kernel (per b, head, 128-row chunk) ----------------
// dyn smem: w1s[4096] w2s[4096] k1t[64*132] gA[128*64] gB[128*64] = 132096 B
__global__ __launch_bounds__(256) void ttt_grad_kernel(
    const float* __restrict__ w1g, const float* __restrict__ w2g)
{
    extern __shared__ float sm[];
    float* w1s = sm;
    float* w2s = sm + 4096;
    float* k1t = sm + 8192;            // [64][132]
    float* gA  = sm + 8192 + 64 * 132; // [128][64]
    float* gB  = gA + 128 * 64;

    const int tid   = threadIdx.x;
    const int chunk = blockIdx.x;   // 0..7
    const int head  = blockIdx.y;   // 0..11
    const int b     = blockIdx.z;   // 0..15
    const int n0    = chunk * 128;

    for (int e = tid * 4; e < 4096; e += 1024) {
        *(float4*)&w1s[e] = *(const float4*)&w1g[head * 4096 + e];
        *(float4*)&w2s[e] = *(const float4*)&w2g[head * 4096 + e];
    }
    {   // k1 transposed: k1t[k][i] = qkv[(b*1024+n0+i), 768 + head*64 + k]
        const float* src = g_qkv + (size_t)(b * N_ + n0) * QC + C_ + head * HD_;
        int i  = tid >> 4;
        int k4 = (tid & 15) * 4;
        for (int p = 0; p < 8; p++, i += 16) {
            float4 v = *(const float4*)(src + (size_t)i * QC + k4);
            k1t[(k4 + 0) * 132 + i] = v.x;
            k1t[(k4 + 1) * 132 + i] = v.y;
            k1t[(k4 + 2) * 132 + i] = v.z;
            k1t[(k4 + 3) * 132 + i] = v.w;
        }
    }
    __syncthreads();

    // Phase 1: A = k1@w1, B = k1@w2 for 8x4 per thread; then elementwise grads
    const int ty = tid >> 4, tx = tid & 15;
    const int i0 = ty * 8, j0 = tx * 4;
    float accA[8][4], accB[8][4];
#pragma unroll
    for (int i = 0; i < 8; i++)
#pragma unroll
        for (int j = 0; j < 4; j++) { accA[i][j] = 0.f; accB[i][j] = 0.f; }

#pragma unroll 8
    for (int kk = 0; kk < 64; kk++) {
        float a[8], b1[4], b2[4];
        *(float4*)&a[0]  = *(float4*)&k1t[kk * 132 + i0];
        *(float4*)&a[4]  = *(float4*)&k1t[kk * 132 + i0 + 4];
        *(float4*)&b1[0] = *(float4*)&w1s[kk * 64 + j0];
        *(float4*)&b2[0] = *(float4*)&w2s[kk * 64 + j0];
#pragma unroll
        for (int i = 0; i < 8; i++)
#pragma unroll
            for (int j = 0; j < 4; j++) {
                accA[i][j] = fmaf(a[i], b1[j], accA[i][j]);
                accB[i][j] = fmaf(a[i], b2[j], accB[i][j]);
            }
    }

    const float* v1p = g_qkv + (size_t)(b * N_ + n0 + i0) * QC + 2 * C_ + head * HD_ + j0;
#pragma unroll
    for (int i = 0; i < 8; i++) {
        float4 vv = *(const float4*)(v1p + (size_t)i * QC);
        float v[4] = {vv.x, vv.y, vv.z, vv.w};
#pragma unroll
        for (int j = 0; j < 4; j++) {
            float Av = accA[i][j], Bv = accB[i][j];
            float sig = 1.f / (1.f + expf(-Bv));
            float sil = Bv * sig;
            float g   = (Av * sil - v[j]) * M1_INV;
            gA[(i0 + i) * 64 + j0 + j] = g * sil;
            gB[(i0 + i) * 64 + j0 + j] = g * Av * sig * (1.f + Bv * (1.f - sig));
        }
    }
    __syncthreads();

    // Phase 2: gw1 = k1^T @ gA, gw2 = k1^T @ gB  (64x64 each, 4x4 per thread)
    const int k0 = ty * 4, jj0 = tx * 4;
    float r1[4][4], r2[4][4];
#pragma unroll
    for (int q = 0; q < 4; q++)
#pragma unroll
        for (int r = 0; r < 4; r++) { r1[q][r] = 0.f; r2[q][r] = 0.f; }

#pragma unroll 4
    for (int i = 0; i < 128; i++) {
        float a[4], bA[4], bB[4];
#pragma unroll
        for (int q = 0; q < 4; q++) a[q] = k1t[(k0 + q) * 132 + i];
        *(float4*)&bA[0] = *(float4*)&gA[i * 64 + jj0];
        *(float4*)&bB[0] = *(float4*)&gB[i * 64 + jj0];
#pragma unroll
        for (int q = 0; q < 4; q++)
#pragma unroll
            for (int r = 0; r < 4; r++) {
                r1[q][r] = fmaf(a[q], bA[r], r1[q][r]);
                r2[q][r] = fmaf(a[q], bB[r], r2[q][r]);
            }
    }

    const int pidx = b * 8 + chunk;  // 0..127
    float* d1 = g_gw_part + ((size_t)(0 * NH + head) * 128 + pidx) * 4096;
    float* d2 = g_gw_part + ((size_t)(1 * NH + head) * 128 + pidx) * 4096;
#pragma unroll
    for (int q = 0; q < 4; q++)
#pragma unroll
        for (int r = 0; r < 4; r++) {
            d1[(k0 + q) * 64 + jj0 + r] = r1[q][r];
            d2[(k0 + q) * 64 + jj0 + r] = r2[q][r];
        }
}

// ---------------- TTT forward kernel (post-update weights) ----------------
// dyn smem: w1s[4096] w2s[4096] k1t[64*132] = 66560 B
__global__ __launch_bounds__(256) void ttt_fwd_kernel()
{
    extern __shared__ float sm[];
    float* w1s = sm;
    float* w2s = sm + 4096;
    float* q1t = sm + 8192;  // [64][132]

    const int tid   = threadIdx.x;
    const int chunk = blockIdx.x;
    const int head  = blockIdx.y;
    const int b     = blockIdx.z;
    const int n0    = chunk * 128;

    for (int e = tid * 4; e < 4096; e += 1024) {
        *(float4*)&w1s[e] = *(const float4*)&g_mw1[head * 4096 + e];
        *(float4*)&w2s[e] = *(const float4*)&g_mw2[head * 4096 + e];
    }
    {   // q1 at col offset head*64
        const float* src = g_qkv + (size_t)(b * N_ + n0) * QC + head * HD_;
        int i  = tid >> 4;
        int k4 = (tid & 15) * 4;
        for (int p = 0; p < 8; p++, i += 16) {
            float4 v = *(const float4*)(src + (size_t)i * QC + k4);
            q1t[(k4 + 0) * 132 + i] = v.x;
            q1t[(k4 + 1) * 132 + i] = v.y;
            q1t[(k4 + 2) * 132 + i] = v.z;
            q1t[(k4 + 3) * 132 + i] = v.w;
        }
    }
    __syncthreads();

    const int ty = tid >> 4, tx = tid & 15;
    const int i0 = ty * 8, j0 = tx * 4;
    float accA[8][4], accB[8][4];
#pragma unroll
    for (int i = 0; i < 8; i++)
#pragma unroll
        for (int j = 0; j < 4; j++) { accA[i][j] = 0.f; accB[i][j] = 0.f; }

#pragma unroll 8
    for (int kk = 0; kk < 64; kk++) {
        float a[8], b1[4], b2[4];
        *(float4*)&a[0]  = *(float4*)&q1t[kk * 132 + i0];
        *(float4*)&a[4]  = *(float4*)&q1t[kk * 132 + i0 + 4];
        *(float4*)&b1[0] = *(float4*)&w1s[kk * 64 + j0];
        *(float4*)&b2[0] = *(float4*)&w2s[kk * 64 + j0];
#pragma unroll
        for (int i = 0; i < 8; i++)
#pragma unroll
            for (int j = 0; j < 4; j++) {
                accA[i][j] = fmaf(a[i], b1[j], accA[i][j]);
                accB[i][j] = fmaf(a[i], b2[j], accB[i][j]);
            }
    }

#pragma unroll
    for (int i = 0; i < 8; i++) {
        float4 o;
        float out[4];
#pragma unroll
        for (int j = 0; j < 4; j++) {
            float Av = accA[i][j], Bv = accB[i][j];
            float sig = 1.f / (1.f + expf(-Bv));
            out[j] = Av * (Bv * sig);
        }
        o.x = out[0]; o.y = out[1]; o.z = out[2]; o.w = out[3];
        *(float4*)(g_xcat + (size_t)(b * N_ + n0 + i0 + i) * XC + head * HD_ + j0) = o;
    }
}

// ---------------- conv grad: per (b, c) plane, partial grad_w3[9] ----------------
__global__ __launch_bounds__(256) void conv_grad_kernel(const float* __restrict__ w3g)
{
    const int bc = blockIdx.x;
    const int b = bc >> 6, c = bc & 63;
    const int tid = threadIdx.x;
    __shared__ float k2s[32][33];
    __shared__ float wk[9];
    __shared__ float red[256];

    if (tid < 9) wk[tid] = w3g[c * 9 + tid];
    const float* base = g_qkv + (size_t)(b * N_) * QC;
    for (int p = tid; p < 1024; p += 256)
        k2s[p >> 5][p & 31] = base[(size_t)p * QC + 2368 + c];
    __syncthreads();

    float acc[9];
#pragma unroll
    for (int q = 0; q < 9; q++) acc[q] = 0.f;

    for (int p = tid; p < 1024; p += 256) {
        const int y = p >> 5, x = p & 31;
        float t[9];
#pragma unroll
        for (int dy = 0; dy < 3; dy++)
#pragma unroll
            for (int dx = 0; dx < 3; dx++) {
                int yy = y + dy - 1, xx = x + dx - 1;
                t[dy * 3 + dx] = (yy >= 0 && yy < 32 && xx >= 0 && xx < 32)
                                 ? k2s[yy][xx] : 0.f;
            }
        float f = 0.f;
#pragma unroll
        for (int q = 0; q < 9; q++) f = fmaf(wk[q], t[q], f);
        float v = base[(size_t)p * QC + 2432 + c];
        float g = (f - v) * M2_INV;
#pragma unroll
        for (int q = 0; q < 9; q++) acc[q] = fmaf(g, t[q], acc[q]);
    }

    for (int q = 0; q < 9; q++) {
        red[tid] = acc[q];
        __syncthreads();
        for (int s = 128; s > 0; s >>= 1) {
            if (tid < s) red[tid] += red[tid + s];
            __syncthreads();
        }
        if (tid == 0) g_gw3_part[(size_t)bc * 9 + q] = red[0];
        __syncthreads();
    }
}

// ---------------- conv grad reduce over batch + sumsq (1 block, 576 thr) -------
__global__ void conv_grad_reduce_kernel()
{
    const int tid = threadIdx.x;  // 576 threads
    __shared__ float red[576];
    float s = 0.f;
    const int c = tid / 9, q = tid % 9;
    for (int b = 0; b < B_; b++) s += g_gw3_part[(size_t)(b * 64 + c) * 9 + q];
    g_gw3[tid] = s;
    red[tid] = s * s;
    __syncthreads();
    if (tid < 64) red[tid] += red[tid + 512];
    __syncthreads();
    for (int st = 256; st > 0; st >>= 1) {
        if (tid < st && tid + st < 576) red[tid] += red[tid + st];
        __syncthreads();
    }
    if (tid == 0) g_sumsq[24] = red[0];
}

// ---------------- reduce gw partials over 128 chunks + per-head sumsq ----------
__global__ __launch_bounds__(256) void reduce_gw_kernel()
{
    const int th  = blockIdx.x;           // 0..23: (tensor*12 + head)
    const int tid = threadIdx.x;
    const float* src = g_gw_part + (size_t)th * 128 * 4096;
    float* dst = g_gw + (size_t)th * 4096;

    float s[16];
#pragma unroll
    for (int q = 0; q < 16; q++) s[q] = 0.f;
    for (int p = 0; p < 128; p++) {
        const float* row = src + (size_t)p * 4096 + tid;
#pragma unroll
        for (int q = 0; q < 16; q++) s[q] += row[q * 256];
    }
    float ss = 0.f;
#pragma unroll
    for (int q = 0; q < 16; q++) { dst[tid + q * 256] = s[q]; ss += s[q] * s[q]; }

    __shared__ float red[256];
    red[tid] = ss;
    __syncthreads();
    for (int st = 128; st > 0; st >>= 1) {
        if (tid < st) red[tid] += red[tid + st];
        __syncthreads();
    }
    if (tid == 0) g_sumsq[th] = red[0];
}

// ---------------- scales ----------------
__global__ void compute_scales_kernel()
{
    if (threadIdx.x == 0) {
        float s1 = 0.f, s2 = 0.f;
        for (int h = 0; h < NH; h++) { s1 += g_sumsq[h]; s2 += g_sumsq[NH + h]; }
        g_scales[0] = LR_ / (sqrtf(s1) + 1.f);
        g_scales[1] = LR_ / (sqrtf(s2) + 1.f);
        g_scales[2] = LR_ / (sqrtf(g_sumsq[24]) + 1.f);
    }
}

// ---------------- weight update ----------------
__global__ void update_w_kernel(const float* __restrict__ w1g,
                                const float* __restrict__ w2g,
                                const float* __restrict__ w3g)
{
    const int i = blockIdx.x * 256 + threadIdx.x;
    if (i < 49152) {
        g_mw1[i] = w1g[i] - g_scales[0] * g_gw[i];
    } else if (i < 98304) {
        const int k = i - 49152;
        g_mw2[k] = w2g[k] - g_scales[1] * g_gw[49152 + k];
    } else if (i < 98880) {
        const int k = i - 98304;
        g_mw3[k] = w3g[k] - g_scales[2] * g_gw3[k];
    }
}

// ---------------- conv forward with updated w3, writes xcat cols 768.. ----------
__global__ __launch_bounds__(256) void conv_fwd_kernel()
{
    const int bc = blockIdx.x;
    const int b = bc >> 6, c = bc & 63;
    const int tid = threadIdx.x;
    __shared__ float q2s[32][33];
    __shared__ float wk[9];
    if (tid < 9) wk[tid] = g_mw3[c * 9 + tid];
    const float* base = g_qkv + (size_t)(b * N_) * QC;
    for (int p = tid; p < 1024; p += 256)
        q2s[p >> 5][p & 31] = base[(size_t)p * QC + 2304 + c];
    __syncthreads();

    for (int p = tid; p < 1024; p += 256) {
        const int y = p >> 5, x = p & 31;
        float f = 0.f;
#pragma unroll
        for (int dy = 0; dy < 3; dy++)
#pragma unroll
            for (int dx = 0; dx < 3; dx++) {
                int yy = y + dy - 1, xx = x + dx - 1;
                if (yy >= 0 && yy < 32 && xx >= 0 && xx < 32)
                    f = fmaf(wk[dy * 3 + dx], q2s[yy][xx], f);
            }
        g_xcat[(size_t)(b * N_ + p) * XC + 768 + c] = f;
    }
}

// ---------------- launch ----------------
extern "C" void kernel_launch(void* const* d_in, const int* in_sizes, int n_in,
                              void* d_out, int out_size)
{
    // Resolve inputs by element count (robust to h/w scalars being present or not)
    const float *x = nullptr, *Wqkv = nullptr, *bqkv = nullptr, *w1 = nullptr,
                *w2 = nullptr, *w3 = nullptr, *Wproj = nullptr, *bproj = nullptr;
    for (int i = 0; i < n_in; i++) {
        const int s = in_sizes[i];
        const float* p = (const float*)d_in[i];
        if      (s == B_*N_*C_)   x = p;
        else if (s == C_*QC)      Wqkv = p;
        else if (s == QC)         bqkv = p;
        else if (s == NH*HD_*HD_) { if (!w1) w1 = p; else w2 = p; }
        else if (s == 64*9)       w3 = p;
        else if (s == XC*C_)      Wproj = p;
        else if (s == C_)         bproj = p;
    }

    float *qkv_ptr, *xcat_ptr;
    cudaGetSymbolAddress((void**)&qkv_ptr, g_qkv);
    cudaGetSymbolAddress((void**)&xcat_ptr, g_xcat);

    cudaFuncSetAttribute(ttt_grad_kernel,
        cudaFuncAttributeMaxDynamicSharedMemorySize, 132096);
    cudaFuncSetAttribute(ttt_fwd_kernel,
        cudaFuncAttributeMaxDynamicSharedMemorySize, 66560);

    // 1. qkv = x @ Wqkv + bqkv   [16384 x 2496]
    {
        dim3 grid((QC + 127) / 128, (B_ * N_) / 128);
        sgemm_bias<<<grid, 256>>>(x, Wqkv, bqkv, qkv_ptr, B_ * N_, QC, C_);
    }
    // 2. TTT gradient partials
    ttt_grad_kernel<<<dim3(8, NH, B_), 256, 132096>>>(w1, w2);
    // 3. conv gradient partials + reduce
    conv_grad_kernel<<<B_ * 64, 256>>>(w3);
    conv_grad_reduce_kernel<<<1, 576>>>();
    // 4. reduce attn grads + sumsq per head
    reduce_gw_kernel<<<24, 256>>>();
    // 5. scales, 6. weight update
    compute_scales_kernel<<<1, 32>>>();
    update_w_kernel<<<(98880 + 255) / 256, 256>>>(w1, w2, w3);
    // 7. post-update TTT forward -> xcat[:, :768]
    ttt_fwd_kernel<<<dim3(8, NH, B_), 256, 66560>>>();
    // 8. post-update conv forward -> xcat[:, 768:832]
    conv_fwd_kernel<<<B_ * 64, 256>>>();
    // 9. out = xcat @ Wproj + bproj   [16384 x 768]
    {
        dim3 grid(C_ / 128, (B_ * N_) / 128);
        sgemm_bias<<<grid, 256>>>(xcat_ptr, Wproj, bproj, (float*)d_out,
                                  B_ * N_, C_, XC);
    }
}

// round 2
// speedup vs baseline: 1.0915x; 1.0915x over previous
#include <cuda_runtime.h>
#include <math.h>

#define B_  16
#define N_  1024
#define C_  768
#define NH  12
#define HD_ 64
#define QC  2496   // 3*768 + 3*64
#define XC  832    // 768 + 64
#define M1_INV (1.0f/12582912.0f)  // b*H*n*d
#define M2_INV (1.0f/1048576.0f)   // b*64*32*32
#define LR_ 0.001f

// ---------------- scratch (static device memory; no allocations) ----------------
__device__ float g_qkv[B_*N_*QC];                 // 163.6 MB
__device__ float g_xcat[B_*N_*XC];                // 54.5 MB
__device__ float g_gw_part[2*NH*128*HD_*HD_];     // 50 MB  (deterministic partials)
__device__ float g_gw_stage[24*8*HD_*HD_];        // 3.1 MB
__device__ float g_gw[2*NH*HD_*HD_];
__device__ float g_gw3_part[B_*64*9];
__device__ float g_gw3[64*9];
__device__ float g_sumsq[25];
__device__ float g_scales[3];
__device__ float g_mw1[NH*HD_*HD_];
__device__ float g_mw2[NH*HD_*HD_];
__device__ float g_mw3[64*9];

// ---------------- packed f32x2 helpers (sm_103a FFMA2 path) ----------------
__device__ __forceinline__ unsigned long long pack_dup(float x) {
    unsigned long long d;
    asm("mov.b64 %0, {%1, %1};" : "=l"(d) : "f"(x));
    return d;
}
__device__ __forceinline__ void fma2(unsigned long long &d,
                                     unsigned long long a,
                                     unsigned long long b) {
    asm("fma.rn.f32x2 %0, %1, %2, %0;" : "+l"(d) : "l"(a), "l"(b));
}
__device__ __forceinline__ float2 unpack2(unsigned long long v) {
    float lo, hi;
    asm("mov.b64 {%0, %1}, %2;" : "=f"(lo), "=f"(hi) : "l"(v));
    return make_float2(lo, hi);
}

// ---------------- generic SGEMM: C = A[MxK] * B[KxN] + bias ----------------
// 128x128 tile, BK=8, 256 threads, 8x8 register tile via packed f32x2.
__global__ __launch_bounds__(256, 2) void sgemm_bias(
    const float* __restrict__ A, const float* __restrict__ Bm,
    const float* __restrict__ bias, float* __restrict__ C,
    int M, int N, int K)
{
    __shared__ float As[8][128];
    __shared__ float Bs[8][128];
    const int tid  = threadIdx.x;
    const int row0 = blockIdx.y * 128;
    const int col0 = blockIdx.x * 128;
    const int ty = tid >> 4, tx = tid & 15;
    const int trow = ty * 8, tcol = tx * 8;
    const int a_r = (tid * 4) >> 3, a_c = (tid * 4) & 7;
    const int b_r = (tid * 4) >> 7, b_c = (tid * 4) & 127;

    unsigned long long acc2[8][4];
#pragma unroll
    for (int i = 0; i < 8; i++)
#pragma unroll
        for (int j = 0; j < 4; j++) acc2[i][j] = 0ULL;

    for (int k0 = 0; k0 < K; k0 += 8) {
        float4 av = *(const float4*)(A + (size_t)(row0 + a_r) * K + k0 + a_c);
        float4 bv = make_float4(0.f, 0.f, 0.f, 0.f);
        if (col0 + b_c < N)
            bv = *(const float4*)(Bm + (size_t)(k0 + b_r) * N + col0 + b_c);
        __syncthreads();
        As[a_c + 0][a_r] = av.x;
        As[a_c + 1][a_r] = av.y;
        As[a_c + 2][a_r] = av.z;
        As[a_c + 3][a_r] = av.w;
        *(float4*)&Bs[b_r][b_c] = bv;
        __syncthreads();
#pragma unroll
        for (int kk = 0; kk < 8; kk++) {
            float a[8];
            *(float4*)&a[0] = *(float4*)&As[kk][trow];
            *(float4*)&a[4] = *(float4*)&As[kk][trow + 4];
            unsigned long long b2[4];
#pragma unroll
            for (int j = 0; j < 4; j++)
                b2[j] = *(const unsigned long long*)&Bs[kk][tcol + 2 * j];
#pragma unroll
            for (int i = 0; i < 8; i++) {
                unsigned long long a2 = pack_dup(a[i]);
#pragma unroll
                for (int j = 0; j < 4; j++) fma2(acc2[i][j], a2, b2[j]);
            }
        }
    }

#pragma unroll
    for (int i = 0; i < 8; i++) {
        const int row = row0 + trow + i;
#pragma unroll
        for (int j = 0; j < 4; j++) {
            const int col = col0 + tcol + 2 * j;
            if (col < N) {
                float2 p = unpack2(acc2[i][j]);
                p.x += bias[col];
                p.y += bias[col + 1];
                *(float2*)(C + (size_t)row * N + col) = p;
            }
        }
    }
}

// ---------------- TTT gradient kernel (per b, head, 128-row chunk) ----------------
__global__ __launch_bounds__(256) void ttt_grad_kernel(
    const float* __restrict__ w1g, const float* __restrict__ w2g)
{
    extern __shared__ float sm[];
    float* w1s = sm;
    float* w2s = sm + 4096;
    float* k1t = sm + 8192;            // [64][132]
    float* gA  = sm + 8192 + 64 * 132; // [128][64]
    float* gB  = gA + 128 * 64;

    const int tid   = threadIdx.x;
    const int chunk = blockIdx.x;
    const int head  = blockIdx.y;
    const int b     = blockIdx.z;
    const int n0    = chunk * 128;

    for (int e = tid * 4; e < 4096; e += 1024) {
        *(float4*)&w1s[e] = *(const float4*)&w1g[head * 4096 + e];
        *(float4*)&w2s[e] = *(const float4*)&w2g[head * 4096 + e];
    }
    {
        const float* src = g_qkv + (size_t)(b * N_ + n0) * QC + C_ + head * HD_;
        int i  = tid >> 4;
        int k4 = (tid & 15) * 4;
        for (int p = 0; p < 8; p++, i += 16) {
            float4 v = *(const float4*)(src + (size_t)i * QC + k4);
            k1t[(k4 + 0) * 132 + i] = v.x;
            k1t[(k4 + 1) * 132 + i] = v.y;
            k1t[(k4 + 2) * 132 + i] = v.z;
            k1t[(k4 + 3) * 132 + i] = v.w;
        }
    }
    __syncthreads();

    const int ty = tid >> 4, tx = tid & 15;
    const int i0 = ty * 8, j0 = tx * 4;
    unsigned long long accA2[8][2], accB2[8][2];
#pragma unroll
    for (int i = 0; i < 8; i++)
#pragma unroll
        for (int j = 0; j < 2; j++) { accA2[i][j] = 0ULL; accB2[i][j] = 0ULL; }

#pragma unroll 8
    for (int kk = 0; kk < 64; kk++) {
        float a[8];
        *(float4*)&a[0] = *(float4*)&k1t[kk * 132 + i0];
        *(float4*)&a[4] = *(float4*)&k1t[kk * 132 + i0 + 4];
        unsigned long long b1[2], b2[2];
        b1[0] = *(const unsigned long long*)&w1s[kk * 64 + j0];
        b1[1] = *(const unsigned long long*)&w1s[kk * 64 + j0 + 2];
        b2[0] = *(const unsigned long long*)&w2s[kk * 64 + j0];
        b2[1] = *(const unsigned long long*)&w2s[kk * 64 + j0 + 2];
#pragma unroll
        for (int i = 0; i < 8; i++) {
            unsigned long long a2 = pack_dup(a[i]);
            fma2(accA2[i][0], a2, b1[0]);
            fma2(accA2[i][1], a2, b1[1]);
            fma2(accB2[i][0], a2, b2[0]);
            fma2(accB2[i][1], a2, b2[1]);
        }
    }

    const float* v1p = g_qkv + (size_t)(b * N_ + n0 + i0) * QC + 2 * C_ + head * HD_ + j0;
#pragma unroll
    for (int i = 0; i < 8; i++) {
        float4 vv = *(const float4*)(v1p + (size_t)i * QC);
        float v[4] = {vv.x, vv.y, vv.z, vv.w};
        float Aarr[4], Barr[4];
        float2 t;
        t = unpack2(accA2[i][0]); Aarr[0] = t.x; Aarr[1] = t.y;
        t = unpack2(accA2[i][1]); Aarr[2] = t.x; Aarr[3] = t.y;
        t = unpack2(accB2[i][0]); Barr[0] = t.x; Barr[1] = t.y;
        t = unpack2(accB2[i][1]); Barr[2] = t.x; Barr[3] = t.y;
#pragma unroll
        for (int j = 0; j < 4; j++) {
            float Av = Aarr[j], Bv = Barr[j];
            float sig = 1.f / (1.f + expf(-Bv));
            float sil = Bv * sig;
            float g   = (Av * sil - v[j]) * M1_INV;
            gA[(i0 + i) * 64 + j0 + j] = g * sil;
            gB[(i0 + i) * 64 + j0 + j] = g * Av * sig * (1.f + Bv * (1.f - sig));
        }
    }
    __syncthreads();

    // Phase 2: gw1 = k1^T @ gA, gw2 = k1^T @ gB
    const int k0 = ty * 4, jj0 = tx * 4;
    unsigned long long r1[4][2], r2[4][2];
#pragma unroll
    for (int q = 0; q < 4; q++)
#pragma unroll
        for (int r = 0; r < 2; r++) { r1[q][r] = 0ULL; r2[q][r] = 0ULL; }

#pragma unroll 4
    for (int i = 0; i < 128; i++) {
        float a[4];
#pragma unroll
        for (int q = 0; q < 4; q++) a[q] = k1t[(k0 + q) * 132 + i];
        unsigned long long bA[2], bB[2];
        bA[0] = *(const unsigned long long*)&gA[i * 64 + jj0];
        bA[1] = *(const unsigned long long*)&gA[i * 64 + jj0 + 2];
        bB[0] = *(const unsigned long long*)&gB[i * 64 + jj0];
        bB[1] = *(const unsigned long long*)&gB[i * 64 + jj0 + 2];
#pragma unroll
        for (int q = 0; q < 4; q++) {
            unsigned long long a2 = pack_dup(a[q]);
            fma2(r1[q][0], a2, bA[0]);
            fma2(r1[q][1], a2, bA[1]);
            fma2(r2[q][0], a2, bB[0]);
            fma2(r2[q][1], a2, bB[1]);
        }
    }

    const int pidx = b * 8 + chunk;
    float* d1 = g_gw_part + ((size_t)(0 * NH + head) * 128 + pidx) * 4096;
    float* d2 = g_gw_part + ((size_t)(1 * NH + head) * 128 + pidx) * 4096;
#pragma unroll
    for (int q = 0; q < 4; q++) {
        float2 p;
        p = unpack2(r1[q][0]); *(float2*)&d1[(k0 + q) * 64 + jj0]     = p;
        p = unpack2(r1[q][1]); *(float2*)&d1[(k0 + q) * 64 + jj0 + 2] = p;
        p = unpack2(r2[q][0]); *(float2*)&d2[(k0 + q) * 64 + jj0]     = p;
        p = unpack2(r2[q][1]); *(float2*)&d2[(k0 + q) * 64 + jj0 + 2] = p;
    }
}

// ---------------- TTT forward kernel (post-update weights) ----------------
__global__ __launch_bounds__(256) void ttt_fwd_kernel()
{
    extern __shared__ float sm[];
    float* w1s = sm;
    float* w2s = sm + 4096;
    float* q1t = sm + 8192;

    const int tid   = threadIdx.x;
    const int chunk = blockIdx.x;
    const int head  = blockIdx.y;
    const int b     = blockIdx.z;
    const int n0    = chunk * 128;

    for (int e = tid * 4; e < 4096; e += 1024) {
        *(float4*)&w1s[e] = *(const float4*)&g_mw1[head * 4096 + e];
        *(float4*)&w2s[e] = *(const float4*)&g_mw2[head * 4096 + e];
    }
    {
        const float* src = g_qkv + (size_t)(b * N_ + n0) * QC + head * HD_;
        int i  = tid >> 4;
        int k4 = (tid & 15) * 4;
        for (int p = 0; p < 8; p++, i += 16) {
            float4 v = *(const float4*)(src + (size_t)i * QC + k4);
            q1t[(k4 + 0) * 132 + i] = v.x;
            q1t[(k4 + 1) * 132 + i] = v.y;
            q1t[(k4 + 2) * 132 + i] = v.z;
            q1t[(k4 + 3) * 132 + i] = v.w;
        }
    }
    __syncthreads();

    const int ty = tid >> 4, tx = tid & 15;
    const int i0 = ty * 8, j0 = tx * 4;
    unsigned long long accA2[8][2], accB2[8][2];
#pragma unroll
    for (int i = 0; i < 8; i++)
#pragma unroll
        for (int j = 0; j < 2; j++) { accA2[i][j] = 0ULL; accB2[i][j] = 0ULL; }

#pragma unroll 8
    for (int kk = 0; kk < 64; kk++) {
        float a[8];
        *(float4*)&a[0] = *(float4*)&q1t[kk * 132 + i0];
        *(float4*)&a[4] = *(float4*)&q1t[kk * 132 + i0 + 4];
        unsigned long long b1[2], b2[2];
        b1[0] = *(const unsigned long long*)&w1s[kk * 64 + j0];
        b1[1] = *(const unsigned long long*)&w1s[kk * 64 + j0 + 2];
        b2[0] = *(const unsigned long long*)&w2s[kk * 64 + j0];
        b2[1] = *(const unsigned long long*)&w2s[kk * 64 + j0 + 2];
#pragma unroll
        for (int i = 0; i < 8; i++) {
            unsigned long long a2 = pack_dup(a[i]);
            fma2(accA2[i][0], a2, b1[0]);
            fma2(accA2[i][1], a2, b1[1]);
            fma2(accB2[i][0], a2, b2[0]);
            fma2(accB2[i][1], a2, b2[1]);
        }
    }

#pragma unroll
    for (int i = 0; i < 8; i++) {
        float Aarr[4], Barr[4];
        float2 t;
        t = unpack2(accA2[i][0]); Aarr[0] = t.x; Aarr[1] = t.y;
        t = unpack2(accA2[i][1]); Aarr[2] = t.x; Aarr[3] = t.y;
        t = unpack2(accB2[i][0]); Barr[0] = t.x; Barr[1] = t.y;
        t = unpack2(accB2[i][1]); Barr[2] = t.x; Barr[3] = t.y;
        float4 o;
        float out[4];
#pragma unroll
        for (int j = 0; j < 4; j++) {
            float sig = 1.f / (1.f + expf(-Barr[j]));
            out[j] = Aarr[j] * (Barr[j] * sig);
        }
        o.x = out[0]; o.y = out[1]; o.z = out[2]; o.w = out[3];
        *(float4*)(g_xcat + (size_t)(b * N_ + n0 + i0 + i) * XC + head * HD_ + j0) = o;
    }
}

// ---------------- conv grad ----------------
__global__ __launch_bounds__(256) void conv_grad_kernel(const float* __restrict__ w3g)
{
    const int bc = blockIdx.x;
    const int b = bc >> 6, c = bc & 63;
    const int tid = threadIdx.x;
    __shared__ float k2s[32][33];
    __shared__ float wk[9];
    __shared__ float red[256];

    if (tid < 9) wk[tid] = w3g[c * 9 + tid];
    const float* base = g_qkv + (size_t)(b * N_) * QC;
    for (int p = tid; p < 1024; p += 256)
        k2s[p >> 5][p & 31] = base[(size_t)p * QC + 2368 + c];
    __syncthreads();

    float acc[9];
#pragma unroll
    for (int q = 0; q < 9; q++) acc[q] = 0.f;

    for (int p = tid; p < 1024; p += 256) {
        const int y = p >> 5, x = p & 31;
        float t[9];
#pragma unroll
        for (int dy = 0; dy < 3; dy++)
#pragma unroll
            for (int dx = 0; dx < 3; dx++) {
                int yy = y + dy - 1, xx = x + dx - 1;
                t[dy * 3 + dx] = (yy >= 0 && yy < 32 && xx >= 0 && xx < 32)
                                 ? k2s[yy][xx] : 0.f;
            }
        float f = 0.f;
#pragma unroll
        for (int q = 0; q < 9; q++) f = fmaf(wk[q], t[q], f);
        float v = base[(size_t)p * QC + 2432 + c];
        float g = (f - v) * M2_INV;
#pragma unroll
        for (int q = 0; q < 9; q++) acc[q] = fmaf(g, t[q], acc[q]);
    }

    for (int q = 0; q < 9; q++) {
        red[tid] = acc[q];
        __syncthreads();
        for (int s = 128; s > 0; s >>= 1) {
            if (tid < s) red[tid] += red[tid + s];
            __syncthreads();
        }
        if (tid == 0) g_gw3_part[(size_t)bc * 9 + q] = red[0];
        __syncthreads();
    }
}

__global__ void conv_grad_reduce_kernel()
{
    const int tid = threadIdx.x;  // 576 threads
    __shared__ float red[576];
    float s = 0.f;
    const int c = tid / 9, q = tid % 9;
    for (int b = 0; b < B_; b++) s += g_gw3_part[(size_t)(b * 64 + c) * 9 + q];
    g_gw3[tid] = s;
    red[tid] = s * s;
    __syncthreads();
    if (tid < 64) red[tid] += red[tid + 512];
    __syncthreads();
    for (int st = 256; st > 0; st >>= 1) {
        if (tid < st && tid + st < 576) red[tid] += red[tid + st];
        __syncthreads();
    }
    if (tid == 0) g_sumsq[24] = red[0];
}

// ---------------- two-stage gw reduce ----------------
__global__ __launch_bounds__(256) void reduce_gw_stage1()
{
    const int th = blockIdx.x >> 3;        // 0..23
    const int g  = blockIdx.x & 7;         // 0..7
    const int tid = threadIdx.x;
    const float* src = g_gw_part + ((size_t)th * 128 + g * 16) * 4096;
    float s[16];
#pragma unroll
    for (int q = 0; q < 16; q++) s[q] = 0.f;
    for (int p = 0; p < 16; p++) {
        const float* row = src + (size_t)p * 4096 + tid;
#pragma unroll
        for (int q = 0; q < 16; q++) s[q] += row[q * 256];
    }
    float* dst = g_gw_stage + (size_t)(th * 8 + g) * 4096 + tid;
#pragma unroll
    for (int q = 0; q < 16; q++) dst[q * 256] = s[q];
}

__global__ __launch_bounds__(256) void reduce_gw_stage2()
{
    const int th  = blockIdx.x;            // 0..23
    const int tid = threadIdx.x;
    const float* src = g_gw_stage + (size_t)th * 8 * 4096;
    float* dst = g_gw + (size_t)th * 4096;

    float s[16];
#pragma unroll
    for (int q = 0; q < 16; q++) s[q] = 0.f;
    for (int p = 0; p < 8; p++) {
        const float* row = src + (size_t)p * 4096 + tid;
#pragma unroll
        for (int q = 0; q < 16; q++) s[q] += row[q * 256];
    }
    float ss = 0.f;
#pragma unroll
    for (int q = 0; q < 16; q++) { dst[tid + q * 256] = s[q]; ss += s[q] * s[q]; }

    __shared__ float red[256];
    red[tid] = ss;
    __syncthreads();
    for (int st = 128; st > 0; st >>= 1) {
        if (tid < st) red[tid] += red[tid + st];
        __syncthreads();
    }
    if (tid == 0) g_sumsq[th] = red[0];
}

// ---------------- scales / update ----------------
__global__ void compute_scales_kernel()
{
    if (threadIdx.x == 0) {
        float s1 = 0.f, s2 = 0.f;
        for (int h = 0; h < NH; h++) { s1 += g_sumsq[h]; s2 += g_sumsq[NH + h]; }
        g_scales[0] = LR_ / (sqrtf(s1) + 1.f);
        g_scales[1] = LR_ / (sqrtf(s2) + 1.f);
        g_scales[2] = LR_ / (sqrtf(g_sumsq[24]) + 1.f);
    }
}

__global__ void update_w_kernel(const float* __restrict__ w1g,
                                const float* __restrict__ w2g,
                                const float* __restrict__ w3g)
{
    const int i = blockIdx.x * 256 + threadIdx.x;
    if (i < 49152) {
        g_mw1[i] = w1g[i] - g_scales[0] * g_gw[i];
    } else if (i < 98304) {
        const int k = i - 49152;
        g_mw2[k] = w2g[k] - g_scales[1] * g_gw[49152 + k];
    } else if (i < 98880) {
        const int k = i - 98304;
        g_mw3[k] = w3g[k] - g_scales[2] * g_gw3[k];
    }
}

// ---------------- conv forward ----------------
__global__ __launch_bounds__(256) void conv_fwd_kernel()
{
    const int bc = blockIdx.x;
    const int b = bc >> 6, c = bc & 63;
    const int tid = threadIdx.x;
    __shared__ float q2s[32][33];
    __shared__ float wk[9];
    if (tid < 9) wk[tid] = g_mw3[c * 9 + tid];
    const float* base = g_qkv + (size_t)(b * N_) * QC;
    for (int p = tid; p < 1024; p += 256)
        q2s[p >> 5][p & 31] = base[(size_t)p * QC + 2304 + c];
    __syncthreads();

    for (int p = tid; p < 1024; p += 256) {
        const int y = p >> 5, x = p & 31;
        float f = 0.f;
#pragma unroll
        for (int dy = 0; dy < 3; dy++)
#pragma unroll
            for (int dx = 0; dx < 3; dx++) {
                int yy = y + dy - 1, xx = x + dx - 1;
                if (yy >= 0 && yy < 32 && xx >= 0 && xx < 32)
                    f = fmaf(wk[dy * 3 + dx], q2s[yy][xx], f);
            }
        g_xcat[(size_t)(b * N_ + p) * XC + 768 + c] = f;
    }
}

// ---------------- launch ----------------
extern "C" void kernel_launch(void* const* d_in, const int* in_sizes, int n_in,
                              void* d_out, int out_size)
{
    const float *x = nullptr, *Wqkv = nullptr, *bqkv = nullptr, *w1 = nullptr,
                *w2 = nullptr, *w3 = nullptr, *Wproj = nullptr, *bproj = nullptr;
    for (int i = 0; i < n_in; i++) {
        const int s = in_sizes[i];
        const float* p = (const float*)d_in[i];
        if      (s == B_*N_*C_)   x = p;
        else if (s == C_*QC)      Wqkv = p;
        else if (s == QC)         bqkv = p;
        else if (s == NH*HD_*HD_) { if (!w1) w1 = p; else w2 = p; }
        else if (s == 64*9)       w3 = p;
        else if (s == XC*C_)      Wproj = p;
        else if (s == C_)         bproj = p;
    }

    float *qkv_ptr, *xcat_ptr;
    cudaGetSymbolAddress((void**)&qkv_ptr, g_qkv);
    cudaGetSymbolAddress((void**)&xcat_ptr, g_xcat);

    cudaFuncSetAttribute(ttt_grad_kernel,
        cudaFuncAttributeMaxDynamicSharedMemorySize, 132096);
    cudaFuncSetAttribute(ttt_fwd_kernel,
        cudaFuncAttributeMaxDynamicSharedMemorySize, 66560);

    {
        dim3 grid((QC + 127) / 128, (B_ * N_) / 128);
        sgemm_bias<<<grid, 256>>>(x, Wqkv, bqkv, qkv_ptr, B_ * N_, QC, C_);
    }
    ttt_grad_kernel<<<dim3(8, NH, B_), 256, 132096>>>(w1, w2);
    conv_grad_kernel<<<B_ * 64, 256>>>(w3);
    conv_grad_reduce_kernel<<<1, 576>>>();
    reduce_gw_stage1<<<192, 256>>>();
    reduce_gw_stage2<<<24, 256>>>();
    compute_scales_kernel<<<1, 32>>>();
    update_w_kernel<<<(98880 + 255) / 256, 256>>>(w1, w2, w3);
    ttt_fwd_kernel<<<dim3(8, NH, B_), 256, 66560>>>();
    conv_fwd_kernel<<<B_ * 64, 256>>>();
    {
        dim3 grid(C_ / 128, (B_ * N_) / 128);
        sgemm_bias<<<grid, 256>>>(xcat_ptr, Wproj, bproj, (float*)d_out,
                                  B_ * N_, C_, XC);
    }
}

// round 7
// speedup vs baseline: 2.3266x; 2.1317x over previous
#include <cuda_runtime.h>
#include <cuda_bf16.h>
#include <cstdint>
#include <cstdio>
#include <math.h>

#define B_  16
#define N_  1024
#define C_  768
#define NH  12
#define HD_ 64
#define QC  2496   // 3*768 + 3*64
#define XC  832    // 768 + 64
#define M1_INV (1.0f/12582912.0f)
#define M2_INV (1.0f/1048576.0f)
#define LR_ 0.001f

// ---------------- scratch ----------------
__device__ float g_qkv[B_*N_*QC];
__device__ float g_xcat[B_*N_*XC];
__device__ float g_gw_part[2*NH*128*HD_*HD_];
__device__ float g_gw_stage[24*8*HD_*HD_];
__device__ float g_gw[2*NH*HD_*HD_];
__device__ float g_gw3_part[B_*64*9];
__device__ float g_gw3[64*9];
__device__ float g_sumsq[25];
__device__ float g_scales[3];
__device__ float g_mw1[NH*HD_*HD_];
__device__ float g_mw2[NH*HD_*HD_];
__device__ float g_mw3[64*9];
// bf16 split operands for tensor-core GEMMs
__device__ __nv_bfloat16 g_xh[B_*N_*C_],  g_xl[B_*N_*C_];
__device__ __nv_bfloat16 g_xch[B_*N_*XC], g_xcl[B_*N_*XC];
__device__ __nv_bfloat16 g_wqh[QC*C_],    g_wql[QC*C_];     // [N=2496][K=768]
__device__ __nv_bfloat16 g_wph[C_*XC],    g_wpl[C_*XC];     // [N=768][K=832]

// ---------------- PTX helpers (sm_80-baseline ISA only; scalar asm operands) ----
__device__ __forceinline__ unsigned int smem_to_u32(const void* smem_ptr) {
    unsigned int addr;
    asm("{ .reg .u64 tmp; cvta.to.shared.u64 tmp, %1; cvt.u32.u64 %0, tmp; }"
        : "=r"(addr) : "l"(smem_ptr));
    return addr;
}
__device__ __forceinline__ void cp_async16(unsigned int saddr, const void* gaddr) {
    asm volatile("cp.async.ca.shared.global [%0], [%1], 16;"
                 :: "r"(saddr), "l"(gaddr) : "memory");
}
__device__ __forceinline__ void cp_commit() {
    asm volatile("cp.async.commit_group;" ::: "memory");
}
__device__ __forceinline__ void cp_wait1() {
    asm volatile("cp.async.wait_group 1;" ::: "memory");
}
__device__ __forceinline__ void cp_wait0() {
    asm volatile("cp.async.wait_group 0;" ::: "memory");
}
__device__ __forceinline__ void ldm_x4(unsigned int& r0, unsigned int& r1,
                                       unsigned int& r2, unsigned int& r3,
                                       unsigned int a) {
    asm volatile("ldmatrix.sync.aligned.m8n8.x4.shared.b16 {%0,%1,%2,%3}, [%4];"
                 : "=r"(r0), "=r"(r1), "=r"(r2), "=r"(r3) : "r"(a));
}
__device__ __forceinline__ void mma_bf16(float& c0, float& c1, float& c2, float& c3,
                                         unsigned int a0, unsigned int a1,
                                         unsigned int a2, unsigned int a3,
                                         unsigned int b0, unsigned int b1) {
    asm volatile("mma.sync.aligned.m16n8k16.row.col.f32.bf16.bf16.f32 "
                 "{%0,%1,%2,%3}, {%4,%5,%6,%7}, {%8,%9}, {%0,%1,%2,%3};"
                 : "+f"(c0), "+f"(c1), "+f"(c2), "+f"(c3)
                 : "r"(a0), "r"(a1), "r"(a2), "r"(a3), "r"(b0), "r"(b1));
}

// ---------------- split / transpose conversions ----------------
__device__ __forceinline__ unsigned int pack_bf2(__nv_bfloat16 a, __nv_bfloat16 b) {
    return (unsigned int)__bfloat16_as_ushort(a) |
           ((unsigned int)__bfloat16_as_ushort(b) << 16);
}
__global__ __launch_bounds__(256) void split_convert(
    const float* __restrict__ X, __nv_bfloat16* __restrict__ H,
    __nv_bfloat16* __restrict__ L, int n4)
{
    int i = blockIdx.x * 256 + threadIdx.x;
    if (i >= n4) return;
    float4 v = ((const float4*)X)[i];
    __nv_bfloat16 h0 = __float2bfloat16(v.x), h1 = __float2bfloat16(v.y);
    __nv_bfloat16 h2 = __float2bfloat16(v.z), h3 = __float2bfloat16(v.w);
    __nv_bfloat16 l0 = __float2bfloat16(v.x - __bfloat162float(h0));
    __nv_bfloat16 l1 = __float2bfloat16(v.y - __bfloat162float(h1));
    __nv_bfloat16 l2 = __float2bfloat16(v.z - __bfloat162float(h2));
    __nv_bfloat16 l3 = __float2bfloat16(v.w - __bfloat162float(h3));
    uint2 hh, ll;
    hh.x = pack_bf2(h0, h1); hh.y = pack_bf2(h2, h3);
    ll.x = pack_bf2(l0, l1); ll.y = pack_bf2(l2, l3);
    ((uint2*)H)[i] = hh;
    ((uint2*)L)[i] = ll;
}
// W[K][N] -> T[N][K] split into hi/lo
__global__ __launch_bounds__(256) void transpose_split(
    const float* __restrict__ W, __nv_bfloat16* __restrict__ Th,
    __nv_bfloat16* __restrict__ Tl, int K, int N)
{
    __shared__ float s[32][33];
    const int n0 = blockIdx.x * 32, k0 = blockIdx.y * 32;
    const int tx = threadIdx.x & 31, ty = threadIdx.x >> 5;
    for (int r = ty; r < 32; r += 8)
        s[r][tx] = W[(size_t)(k0 + r) * N + n0 + tx];
    __syncthreads();
    for (int r = ty; r < 32; r += 8) {
        float v = s[tx][r];
        __nv_bfloat16 h = __float2bfloat16(v);
        Th[(size_t)(n0 + r) * K + k0 + tx] = h;
        Tl[(size_t)(n0 + r) * K + k0 + tx] = __float2bfloat16(v - __bfloat162float(h));
    }
}

// ---------------- HMMA GEMM: C[M,Nfull] = A[M,K] @ Bt[Nfull,K]^T + bias ---------
// A/B bf16 hi/lo split, 3-term accumulation (A_h*B_h + A_h*B_l + A_l*B_h).
// Block tile 128x128, BK=32, 8 warps (64x32 each), cp.async double buffering.
// SMEM per stage: 4 arrays x 128 rows x 40 bf16 (80B padded, conflict-free
// for ldmatrix: word stride 20 mod 32 covers all banks). 2 stages = 81920 B.
#define SROW   40
#define ARR_B  (128*SROW*2)       // 10240 bytes per array
#define STG_B  (4*ARR_B)          // 40960 bytes per stage
#define TCG_SMEM (2*STG_B)        // 81920

__global__ __launch_bounds__(256) void tc_gemm(
    const __nv_bfloat16* __restrict__ Ah, const __nv_bfloat16* __restrict__ Al,
    const __nv_bfloat16* __restrict__ Bh, const __nv_bfloat16* __restrict__ Bl,
    const float* __restrict__ bias, float* __restrict__ C,
    int Nfull, int K)
{
    extern __shared__ __nv_bfloat16 smb[];
    const unsigned int smem_u = smem_to_u32(smb);
    const int t = threadIdx.x, lane = t & 31, wid = t >> 5;
    const int m0 = blockIdx.y * 128, n0 = blockIdx.x * 128;
    const int wm = (wid >> 2) * 64, wn = (wid & 3) * 32;

    float acc[4][4][4];
#pragma unroll
    for (int a = 0; a < 4; a++)
#pragma unroll
        for (int b = 0; b < 4; b++)
#pragma unroll
            for (int c = 0; c < 4; c++) acc[a][b][c] = 0.f;

    // ---- load plan: 2048 16B-chunks per stage, 8 per thread ----
    const __nv_bfloat16* gp[8];
    unsigned int soff[8];
    bool vld[8];
#pragma unroll
    for (int p = 0; p < 8; p++) {
        int c = p * 256 + t;
        int arr = c >> 9, rem = c & 511, row = rem >> 2, c4 = rem & 3;
        const __nv_bfloat16* base = (arr == 0) ? Ah : (arr == 1) ? Al
                                   : (arr == 2) ? Bh : Bl;
        int grow = (arr < 2) ? (m0 + row) : (n0 + row);
        vld[p]  = (arr < 2) || ((n0 + row) < Nfull);
        if (!vld[p]) grow = 0;
        gp[p]   = base + (size_t)grow * K + c4 * 8;
        soff[p] = (unsigned int)(arr * ARR_B + (row * SROW + c4 * 8) * 2);
    }

#define ISSUE(stg, ks) do {                                             \
        unsigned int _sb = smem_u + (unsigned int)(stg) * STG_B;        \
        _Pragma("unroll")                                               \
        for (int p = 0; p < 8; p++)                                     \
            if (vld[p]) cp_async16(_sb + soff[p], gp[p] + (ks) * 32);   \
        cp_commit();                                                    \
    } while (0)

    const int nk = K / 32;
    ISSUE(0, 0);

    for (int s = 0; s < nk; s++) {
        if (s + 1 < nk) { ISSUE((s + 1) & 1, s + 1); cp_wait1(); }
        else            { cp_wait0(); }
        __syncthreads();

        const unsigned int sb = smem_u + (unsigned int)(s & 1) * STG_B;
#pragma unroll
        for (int kc = 0; kc < 32; kc += 16) {
            // B fragments (hi & lo): 4 n-tiles of n8k16
            unsigned int bh[4][2], bl[4][2];
#pragma unroll
            for (int q = 0; q < 2; q++) {
                unsigned int brow = (unsigned int)(wn + q * 16 + (lane & 7) +
                                                   ((lane >> 4) << 3));
                unsigned int koff = (unsigned int)(((lane >> 3) & 1) * 8);
                unsigned int ab = sb + 2u * ARR_B + (brow * SROW + kc + koff) * 2;
                ldm_x4(bh[2*q][0], bh[2*q][1], bh[2*q+1][0], bh[2*q+1][1], ab);
                ldm_x4(bl[2*q][0], bl[2*q][1], bl[2*q+1][0], bl[2*q+1][1],
                       ab + ARR_B);
            }
#pragma unroll
            for (int mt = 0; mt < 4; mt++) {
                unsigned int arow = (unsigned int)(wm + mt * 16 + (lane & 15));
                unsigned int koff = (unsigned int)((lane >> 4) * 8);
                unsigned int aa = sb + (arow * SROW + kc + koff) * 2;
                unsigned int ah0, ah1, ah2, ah3, al0, al1, al2, al3;
                ldm_x4(ah0, ah1, ah2, ah3, aa);
                ldm_x4(al0, al1, al2, al3, aa + ARR_B);
#pragma unroll
                for (int nt = 0; nt < 4; nt++) {
                    mma_bf16(acc[mt][nt][0], acc[mt][nt][1],
                             acc[mt][nt][2], acc[mt][nt][3],
                             ah0, ah1, ah2, ah3, bh[nt][0], bh[nt][1]);
                    mma_bf16(acc[mt][nt][0], acc[mt][nt][1],
                             acc[mt][nt][2], acc[mt][nt][3],
                             ah0, ah1, ah2, ah3, bl[nt][0], bl[nt][1]);
                    mma_bf16(acc[mt][nt][0], acc[mt][nt][1],
                             acc[mt][nt][2], acc[mt][nt][3],
                             al0, al1, al2, al3, bh[nt][0], bh[nt][1]);
                }
            }
        }
        __syncthreads();
    }
#undef ISSUE

    // ---- epilogue ----
    const int g = lane >> 2, tq = lane & 3;
#pragma unroll
    for (int mt = 0; mt < 4; mt++) {
        const int row = m0 + wm + mt * 16 + g;
#pragma unroll
        for (int nt = 0; nt < 4; nt++) {
            const int col = n0 + wn + nt * 8 + tq * 2;
            if (col < Nfull) {
                float b0 = bias[col], b1 = bias[col + 1];
                float2 o1; o1.x = acc[mt][nt][0] + b0; o1.y = acc[mt][nt][1] + b1;
                float2 o2; o2.x = acc[mt][nt][2] + b0; o2.y = acc[mt][nt][3] + b1;
                *(float2*)(C + (size_t)row * Nfull + col) = o1;
                *(float2*)(C + (size_t)(row + 8) * Nfull + col) = o2;
            }
        }
    }
}

// ---------------- packed f32x2 helpers ----------------
__device__ __forceinline__ unsigned long long pack_dup(float x) {
    unsigned long long d;
    asm("mov.b64 %0, {%1, %1};" : "=l"(d) : "f"(x));
    return d;
}
__device__ __forceinline__ void fma2(unsigned long long &d,
                                     unsigned long long a, unsigned long long b) {
    asm("fma.rn.f32x2 %0, %1, %2, %0;" : "+l"(d) : "l"(a), "l"(b));
}
__device__ __forceinline__ float2 unpack2(unsigned long long v) {
    float lo, hi;
    asm("mov.b64 {%0, %1}, %2;" : "=f"(lo), "=f"(hi) : "l"(v));
    return make_float2(lo, hi);
}

// ---------------- TTT gradient kernel ----------------
__global__ __launch_bounds__(256) void ttt_grad_kernel(
    const float* __restrict__ w1g, const float* __restrict__ w2g)
{
    extern __shared__ float sm_f[];
    float* w1s = sm_f;
    float* w2s = sm_f + 4096;
    float* k1t = sm_f + 8192;
    float* gA  = sm_f + 8192 + 64 * 132;
    float* gB  = gA + 128 * 64;

    const int tid   = threadIdx.x;
    const int chunk = blockIdx.x;
    const int head  = blockIdx.y;
    const int b     = blockIdx.z;
    const int n0    = chunk * 128;

    for (int e = tid * 4; e < 4096; e += 1024) {
        *(float4*)&w1s[e] = *(const float4*)&w1g[head * 4096 + e];
        *(float4*)&w2s[e] = *(const float4*)&w2g[head * 4096 + e];
    }
    {
        const float* src = g_qkv + (size_t)(b * N_ + n0) * QC + C_ + head * HD_;
        int i  = tid >> 4;
        int k4 = (tid & 15) * 4;
        for (int p = 0; p < 8; p++, i += 16) {
            float4 v = *(const float4*)(src + (size_t)i * QC + k4);
            k1t[(k4 + 0) * 132 + i] = v.x;
            k1t[(k4 + 1) * 132 + i] = v.y;
            k1t[(k4 + 2) * 132 + i] = v.z;
            k1t[(k4 + 3) * 132 + i] = v.w;
        }
    }
    __syncthreads();

    const int ty = tid >> 4, tx = tid & 15;
    const int i0 = ty * 8, j0 = tx * 4;
    unsigned long long accA2[8][2], accB2[8][2];
#pragma unroll
    for (int i = 0; i < 8; i++)
#pragma unroll
        for (int j = 0; j < 2; j++) { accA2[i][j] = 0ULL; accB2[i][j] = 0ULL; }

#pragma unroll 8
    for (int kk = 0; kk < 64; kk++) {
        float a[8];
        *(float4*)&a[0] = *(float4*)&k1t[kk * 132 + i0];
        *(float4*)&a[4] = *(float4*)&k1t[kk * 132 + i0 + 4];
        unsigned long long b1[2], b2[2];
        b1[0] = *(const unsigned long long*)&w1s[kk * 64 + j0];
        b1[1] = *(const unsigned long long*)&w1s[kk * 64 + j0 + 2];
        b2[0] = *(const unsigned long long*)&w2s[kk * 64 + j0];
        b2[1] = *(const unsigned long long*)&w2s[kk * 64 + j0 + 2];
#pragma unroll
        for (int i = 0; i < 8; i++) {
            unsigned long long a2 = pack_dup(a[i]);
            fma2(accA2[i][0], a2, b1[0]);
            fma2(accA2[i][1], a2, b1[1]);
            fma2(accB2[i][0], a2, b2[0]);
            fma2(accB2[i][1], a2, b2[1]);
        }
    }

    const float* v1p = g_qkv + (size_t)(b * N_ + n0 + i0) * QC + 2 * C_ + head * HD_ + j0;
#pragma unroll
    for (int i = 0; i < 8; i++) {
        float4 vv = *(const float4*)(v1p + (size_t)i * QC);
        float v[4] = {vv.x, vv.y, vv.z, vv.w};
        float Aarr[4], Barr[4];
        float2 tt;
        tt = unpack2(accA2[i][0]); Aarr[0] = tt.x; Aarr[1] = tt.y;
        tt = unpack2(accA2[i][1]); Aarr[2] = tt.x; Aarr[3] = tt.y;
        tt = unpack2(accB2[i][0]); Barr[0] = tt.x; Barr[1] = tt.y;
        tt = unpack2(accB2[i][1]); Barr[2] = tt.x; Barr[3] = tt.y;
#pragma unroll
        for (int j = 0; j < 4; j++) {
            float Av = Aarr[j], Bv = Barr[j];
            float sig = 1.f / (1.f + expf(-Bv));
            float sil = Bv * sig;
            float g   = (Av * sil - v[j]) * M1_INV;
            gA[(i0 + i) * 64 + j0 + j] = g * sil;
            gB[(i0 + i) * 64 + j0 + j] = g * Av * sig * (1.f + Bv * (1.f - sig));
        }
    }
    __syncthreads();

    const int k0 = ty * 4, jj0 = tx * 4;
    unsigned long long r1[4][2], r2[4][2];
#pragma unroll
    for (int q = 0; q < 4; q++)
#pragma unroll
        for (int r = 0; r < 2; r++) { r1[q][r] = 0ULL; r2[q][r] = 0ULL; }

#pragma unroll 4
    for (int i = 0; i < 128; i++) {
        float a[4];
#pragma unroll
        for (int q = 0; q < 4; q++) a[q] = k1t[(k0 + q) * 132 + i];
        unsigned long long bA[2], bB[2];
        bA[0] = *(const unsigned long long*)&gA[i * 64 + jj0];
        bA[1] = *(const unsigned long long*)&gA[i * 64 + jj0 + 2];
        bB[0] = *(const unsigned long long*)&gB[i * 64 + jj0];
        bB[1] = *(const unsigned long long*)&gB[i * 64 + jj0 + 2];
#pragma unroll
        for (int q = 0; q < 4; q++) {
            unsigned long long a2 = pack_dup(a[q]);
            fma2(r1[q][0], a2, bA[0]);
            fma2(r1[q][1], a2, bA[1]);
            fma2(r2[q][0], a2, bB[0]);
            fma2(r2[q][1], a2, bB[1]);
        }
    }

    const int pidx = b * 8 + chunk;
    float* d1 = g_gw_part + ((size_t)(0 * NH + head) * 128 + pidx) * 4096;
    float* d2 = g_gw_part + ((size_t)(1 * NH + head) * 128 + pidx) * 4096;
#pragma unroll
    for (int q = 0; q < 4; q++) {
        float2 p;
        p = unpack2(r1[q][0]); *(float2*)&d1[(k0 + q) * 64 + jj0]     = p;
        p = unpack2(r1[q][1]); *(float2*)&d1[(k0 + q) * 64 + jj0 + 2] = p;
        p = unpack2(r2[q][0]); *(float2*)&d2[(k0 + q) * 64 + jj0]     = p;
        p = unpack2(r2[q][1]); *(float2*)&d2[(k0 + q) * 64 + jj0 + 2] = p;
    }
}

// ---------------- TTT forward kernel ----------------
__global__ __launch_bounds__(256) void ttt_fwd_kernel()
{
    extern __shared__ float sm_f[];
    float* w1s = sm_f;
    float* w2s = sm_f + 4096;
    float* q1t = sm_f + 8192;

    const int tid   = threadIdx.x;
    const int chunk = blockIdx.x;
    const int head  = blockIdx.y;
    const int b     = blockIdx.z;
    const int n0    = chunk * 128;

    for (int e = tid * 4; e < 4096; e += 1024) {
        *(float4*)&w1s[e] = *(const float4*)&g_mw1[head * 4096 + e];
        *(float4*)&w2s[e] = *(const float4*)&g_mw2[head * 4096 + e];
    }
    {
        const float* src = g_qkv + (size_t)(b * N_ + n0) * QC + head * HD_;
        int i  = tid >> 4;
        int k4 = (tid & 15) * 4;
        for (int p = 0; p < 8; p++, i += 16) {
            float4 v = *(const float4*)(src + (size_t)i * QC + k4);
            q1t[(k4 + 0) * 132 + i] = v.x;
            q1t[(k4 + 1) * 132 + i] = v.y;
            q1t[(k4 + 2) * 132 + i] = v.z;
            q1t[(k4 + 3) * 132 + i] = v.w;
        }
    }
    __syncthreads();

    const int ty = tid >> 4, tx = tid & 15;
    const int i0 = ty * 8, j0 = tx * 4;
    unsigned long long accA2[8][2], accB2[8][2];
#pragma unroll
    for (int i = 0; i < 8; i++)
#pragma unroll
        for (int j = 0; j < 2; j++) { accA2[i][j] = 0ULL; accB2[i][j] = 0ULL; }

#pragma unroll 8
    for (int kk = 0; kk < 64; kk++) {
        float a[8];
        *(float4*)&a[0] = *(float4*)&q1t[kk * 132 + i0];
        *(float4*)&a[4] = *(float4*)&q1t[kk * 132 + i0 + 4];
        unsigned long long b1[2], b2[2];
        b1[0] = *(const unsigned long long*)&w1s[kk * 64 + j0];
        b1[1] = *(const unsigned long long*)&w1s[kk * 64 + j0 + 2];
        b2[0] = *(const unsigned long long*)&w2s[kk * 64 + j0];
        b2[1] = *(const unsigned long long*)&w2s[kk * 64 + j0 + 2];
#pragma unroll
        for (int i = 0; i < 8; i++) {
            unsigned long long a2 = pack_dup(a[i]);
            fma2(accA2[i][0], a2, b1[0]);
            fma2(accA2[i][1], a2, b1[1]);
            fma2(accB2[i][0], a2, b2[0]);
            fma2(accB2[i][1], a2, b2[1]);
        }
    }

#pragma unroll
    for (int i = 0; i < 8; i++) {
        float Aarr[4], Barr[4];
        float2 tt;
        tt = unpack2(accA2[i][0]); Aarr[0] = tt.x; Aarr[1] = tt.y;
        tt = unpack2(accA2[i][1]); Aarr[2] = tt.x; Aarr[3] = tt.y;
        tt = unpack2(accB2[i][0]); Barr[0] = tt.x; Barr[1] = tt.y;
        tt = unpack2(accB2[i][1]); Barr[2] = tt.x; Barr[3] = tt.y;
        float4 o;
        float out[4];
#pragma unroll
        for (int j = 0; j < 4; j++) {
            float sig = 1.f / (1.f + expf(-Barr[j]));
            out[j] = Aarr[j] * (Barr[j] * sig);
        }
        o.x = out[0]; o.y = out[1]; o.z = out[2]; o.w = out[3];
        *(float4*)(g_xcat + (size_t)(b * N_ + n0 + i0 + i) * XC + head * HD_ + j0) = o;
    }
}

// ---------------- conv grad ----------------
__global__ __launch_bounds__(256) void conv_grad_kernel(const float* __restrict__ w3g)
{
    const int bc = blockIdx.x;
    const int b = bc >> 6, c = bc & 63;
    const int tid = threadIdx.x;
    __shared__ float k2s[32][33];
    __shared__ float wk[9];
    __shared__ float red[256];

    if (tid < 9) wk[tid] = w3g[c * 9 + tid];
    const float* base = g_qkv + (size_t)(b * N_) * QC;
    for (int p = tid; p < 1024; p += 256)
        k2s[p >> 5][p & 31] = base[(size_t)p * QC + 2368 + c];
    __syncthreads();

    float acc[9];
#pragma unroll
    for (int q = 0; q < 9; q++) acc[q] = 0.f;

    for (int p = tid; p < 1024; p += 256) {
        const int y = p >> 5, x = p & 31;
        float t[9];
#pragma unroll
        for (int dy = 0; dy < 3; dy++)
#pragma unroll
            for (int dx = 0; dx < 3; dx++) {
                int yy = y + dy - 1, xx = x + dx - 1;
                t[dy * 3 + dx] = (yy >= 0 && yy < 32 && xx >= 0 && xx < 32)
                                 ? k2s[yy][xx] : 0.f;
            }
        float f = 0.f;
#pragma unroll
        for (int q = 0; q < 9; q++) f = fmaf(wk[q], t[q], f);
        float v = base[(size_t)p * QC + 2432 + c];
        float g = (f - v) * M2_INV;
#pragma unroll
        for (int q = 0; q < 9; q++) acc[q] = fmaf(g, t[q], acc[q]);
    }

    for (int q = 0; q < 9; q++) {
        red[tid] = acc[q];
        __syncthreads();
        for (int s = 128; s > 0; s >>= 1) {
            if (tid < s) red[tid] += red[tid + s];
            __syncthreads();
        }
        if (tid == 0) g_gw3_part[(size_t)bc * 9 + q] = red[0];
        __syncthreads();
    }
}

__global__ void conv_grad_reduce_kernel()
{
    const int tid = threadIdx.x;
    __shared__ float red[576];
    float s = 0.f;
    const int c = tid / 9, q = tid % 9;
    for (int b = 0; b < B_; b++) s += g_gw3_part[(size_t)(b * 64 + c) * 9 + q];
    g_gw3[tid] = s;
    red[tid] = s * s;
    __syncthreads();
    if (tid < 64) red[tid] += red[tid + 512];
    __syncthreads();
    for (int st = 256; st > 0; st >>= 1) {
        if (tid < st && tid + st < 576) red[tid] += red[tid + st];
        __syncthreads();
    }
    if (tid == 0) g_sumsq[24] = red[0];
}

// ---------------- two-stage gw reduce ----------------
__global__ __launch_bounds__(256) void reduce_gw_stage1()
{
    const int th = blockIdx.x >> 3;
    const int g  = blockIdx.x & 7;
    const int tid = threadIdx.x;
    const float* src = g_gw_part + ((size_t)th * 128 + g * 16) * 4096;
    float s[16];
#pragma unroll
    for (int q = 0; q < 16; q++) s[q] = 0.f;
    for (int p = 0; p < 16; p++) {
        const float* row = src + (size_t)p * 4096 + tid;
#pragma unroll
        for (int q = 0; q < 16; q++) s[q] += row[q * 256];
    }
    float* dst = g_gw_stage + (size_t)(th * 8 + g) * 4096 + tid;
#pragma unroll
    for (int q = 0; q < 16; q++) dst[q * 256] = s[q];
}

__global__ __launch_bounds__(256) void reduce_gw_stage2()
{
    const int th  = blockIdx.x;
    const int tid = threadIdx.x;
    const float* src = g_gw_stage + (size_t)th * 8 * 4096;
    float* dst = g_gw + (size_t)th * 4096;

    float s[16];
#pragma unroll
    for (int q = 0; q < 16; q++) s[q] = 0.f;
    for (int p = 0; p < 8; p++) {
        const float* row = src + (size_t)p * 4096 + tid;
#pragma unroll
        for (int q = 0; q < 16; q++) s[q] += row[q * 256];
    }
    float ss = 0.f;
#pragma unroll
    for (int q = 0; q < 16; q++) { dst[tid + q * 256] = s[q]; ss += s[q] * s[q]; }

    __shared__ float red[256];
    red[tid] = ss;
    __syncthreads();
    for (int st = 128; st > 0; st >>= 1) {
        if (tid < st) red[tid] += red[tid + st];
        __syncthreads();
    }
    if (tid == 0) g_sumsq[th] = red[0];
}

// ---------------- scales / update ----------------
__global__ void compute_scales_kernel()
{
    if (threadIdx.x == 0) {
        float s1 = 0.f, s2 = 0.f;
        for (int h = 0; h < NH; h++) { s1 += g_sumsq[h]; s2 += g_sumsq[NH + h]; }
        g_scales[0] = LR_ / (sqrtf(s1) + 1.f);
        g_scales[1] = LR_ / (sqrtf(s2) + 1.f);
        g_scales[2] = LR_ / (sqrtf(g_sumsq[24]) + 1.f);
    }
}

__global__ void update_w_kernel(const float* __restrict__ w1g,
                                const float* __restrict__ w2g,
                                const float* __restrict__ w3g)
{
    const int i = blockIdx.x * 256 + threadIdx.x;
    if (i < 49152) {
        g_mw1[i] = w1g[i] - g_scales[0] * g_gw[i];
    } else if (i < 98304) {
        const int k = i - 49152;
        g_mw2[k] = w2g[k] - g_scales[1] * g_gw[49152 + k];
    } else if (i < 98880) {
        const int k = i - 98304;
        g_mw3[k] = w3g[k] - g_scales[2] * g_gw3[k];
    }
}

// ---------------- conv forward ----------------
__global__ __launch_bounds__(256) void conv_fwd_kernel()
{
    const int bc = blockIdx.x;
    const int b = bc >> 6, c = bc & 63;
    const int tid = threadIdx.x;
    __shared__ float q2s[32][33];
    __shared__ float wk[9];
    if (tid < 9) wk[tid] = g_mw3[c * 9 + tid];
    const float* base = g_qkv + (size_t)(b * N_) * QC;
    for (int p = tid; p < 1024; p += 256)
        q2s[p >> 5][p & 31] = base[(size_t)p * QC + 2304 + c];
    __syncthreads();

    for (int p = tid; p < 1024; p += 256) {
        const int y = p >> 5, x = p & 31;
        float f = 0.f;
#pragma unroll
        for (int dy = 0; dy < 3; dy++)
#pragma unroll
            for (int dx = 0; dx < 3; dx++) {
                int yy = y + dy - 1, xx = x + dx - 1;
                if (yy >= 0 && yy < 32 && xx >= 0 && xx < 32)
                    f = fmaf(wk[dy * 3 + dx], q2s[yy][xx], f);
            }
        g_xcat[(size_t)(b * N_ + p) * XC + 768 + c] = f;
    }
}

// ---------------- launch ----------------
extern "C" void kernel_launch(void* const* d_in, const int* in_sizes, int n_in,
                              void* d_out, int out_size)
{
    const float *x = nullptr, *Wqkv = nullptr, *bqkv = nullptr, *w1 = nullptr,
                *w2 = nullptr, *w3 = nullptr, *Wproj = nullptr, *bproj = nullptr;
    for (int i = 0; i < n_in; i++) {
        const int s = in_sizes[i];
        const float* p = (const float*)d_in[i];
        if      (s == B_*N_*C_)   x = p;
        else if (s == C_*QC)      Wqkv = p;
        else if (s == QC)         bqkv = p;
        else if (s == NH*HD_*HD_) { if (!w1) w1 = p; else w2 = p; }
        else if (s == 64*9)       w3 = p;
        else if (s == XC*C_)      Wproj = p;
        else if (s == C_)         bproj = p;
    }

    float* qkv_ptr = nullptr;
    float* xcat_ptr = nullptr;
    __nv_bfloat16 *xh, *xl, *xch, *xcl, *wqh, *wql, *wph, *wpl;
    cudaGetSymbolAddress((void**)&qkv_ptr,  g_qkv);
    cudaGetSymbolAddress((void**)&xcat_ptr, g_xcat);
    cudaGetSymbolAddress((void**)&xh,  g_xh);
    cudaGetSymbolAddress((void**)&xl,  g_xl);
    cudaGetSymbolAddress((void**)&xch, g_xch);
    cudaGetSymbolAddress((void**)&xcl, g_xcl);
    cudaGetSymbolAddress((void**)&wqh, g_wqh);
    cudaGetSymbolAddress((void**)&wql, g_wql);
    cudaGetSymbolAddress((void**)&wph, g_wph);
    cudaGetSymbolAddress((void**)&wpl, g_wpl);

    cudaFuncSetAttribute(ttt_grad_kernel,
        cudaFuncAttributeMaxDynamicSharedMemorySize, 132096);
    cudaFuncSetAttribute(ttt_fwd_kernel,
        cudaFuncAttributeMaxDynamicSharedMemorySize, 66560);
    cudaFuncSetAttribute(tc_gemm,
        cudaFuncAttributeMaxDynamicSharedMemorySize, TCG_SMEM);

    // 1. split x, transpose+split weights
    split_convert<<<(B_*N_*C_/4 + 255)/256, 256>>>(x, xh, xl, B_*N_*C_/4);
    transpose_split<<<dim3(QC/32, C_/32), 256>>>(Wqkv, wqh, wql, C_, QC);
    transpose_split<<<dim3(C_/32, XC/32), 256>>>(Wproj, wph, wpl, XC, C_);

    // 2. qkv = x @ Wqkv + bqkv  (HMMA, 3-term bf16 split)
    tc_gemm<<<dim3((QC + 127)/128, (B_*N_)/128), 256, TCG_SMEM>>>(
        xh, xl, wqh, wql, bqkv, qkv_ptr, QC, C_);

    // 3. TTT + conv gradients, reduce, scales, update
    ttt_grad_kernel<<<dim3(8, NH, B_), 256, 132096>>>(w1, w2);
    conv_grad_kernel<<<B_ * 64, 256>>>(w3);
    conv_grad_reduce_kernel<<<1, 576>>>();
    reduce_gw_stage1<<<192, 256>>>();
    reduce_gw_stage2<<<24, 256>>>();
    compute_scales_kernel<<<1, 32>>>();
    update_w_kernel<<<(98880 + 255)/256, 256>>>(w1, w2, w3);

    // 4. post-update forward
    ttt_fwd_kernel<<<dim3(8, NH, B_), 256, 66560>>>();
    conv_fwd_kernel<<<B_ * 64, 256>>>();

    // 5. split xcat, proj GEMM
    split_convert<<<(B_*N_*XC/4 + 255)/256, 256>>>(xcat_ptr, xch, xcl, B_*N_*XC/4);
    tc_gemm<<<dim3(C_/128, (B_*N_)/128), 256, TCG_SMEM>>>(
        xch, xcl, wph, wpl, bproj, (float*)d_out, C_, XC);
}